// round 6
// baseline (speedup 1.0000x reference)
#include <cuda_runtime.h>
#include <math.h>

#define BB   1024
#define NN   40
#define ETAD 64
#define KK   32
#define ZDIM 32
#define NA   10
#define NB   5
#define CH   128
#define AH   128
#define BH   64
#define NODES (BB*NN)        /* 40960 */
#define EPB   780            /* C(40,2) edges per batch */
#define HPAIR 390
#define ZPAD  36             /* padded row stride (floats), 16B aligned */

/* ---- scratch (static device memory; allocation-free) ---- */
__device__ __align__(16) float g_s[BB*KK];
__device__ __align__(16) float g_z[NODES*ZDIM];
__device__ __align__(16) float g_wsym[NB*ZDIM*ZDIM];

/* ---- f32x2 packed helpers (sm_100+) ---- */
__device__ __forceinline__ unsigned long long pk2(float lo, float hi) {
    unsigned long long r;
    asm("mov.b64 %0, {%1, %2};" : "=l"(r) : "f"(lo), "f"(hi));
    return r;
}
__device__ __forceinline__ void upk2(unsigned long long v, float& lo, float& hi) {
    asm("mov.b64 {%0, %1}, %2;" : "=f"(lo), "=f"(hi) : "l"(v));
}
__device__ __forceinline__ unsigned long long fma2(unsigned long long a,
                                                   unsigned long long b,
                                                   unsigned long long c) {
    unsigned long long r;
    asm("fma.rn.f32x2 %0, %1, %2, %3;" : "=l"(r) : "l"(a), "l"(b), "l"(c));
    return r;
}

/* decode lex-order pair index e (0..779) -> (i, j), i<j<NN */
__device__ __forceinline__ void edecode(int e, int& i, int& j) {
    float sq = sqrtf((float)(6241 - 8*e));          /* (2N-1)^2 - 8e */
    i = (int)((79.0f - sq) * 0.5f);
    /* fixup for fp rounding */
    int cum = i*(79 - i)/2;
    if (e < cum)            { i--; cum = i*(79 - i)/2; }
    else if (e >= (i+1)*(78 - i)/2 + (79 - 2*i - 1) ) { /* cheap guard below instead */ }
    int nxt = (i+1)*(79 - (i+1))/2;
    if (e >= nxt)           { i++; cum = nxt; }
    j = i + 1 + (e - cum);
}

/* ---------------- kernel 0: Wsym = 0.5*(W + W^T) ---------------- */
__global__ void k_wsym(const float* __restrict__ bm) {
    int i = blockIdx.x * blockDim.x + threadIdx.x;
    if (i < NB*ZDIM*ZDIM) {
        int t = i / (ZDIM*ZDIM);
        int r = (i / ZDIM) % ZDIM;
        int c = i % ZDIM;
        g_wsym[i] = 0.5f * (bm[t*ZDIM*ZDIM + r*ZDIM + c] +
                            bm[t*ZDIM*ZDIM + c*ZDIM + r]);
    }
}

/* -------- kernel 1: per-batch cluster resblock logits s[b,k] -------- */
__global__ void k_cluster(const float* __restrict__ eta,
                          const float* __restrict__ cW1, const float* __restrict__ cb1,
                          const float* __restrict__ cW2, const float* __restrict__ cb2,
                          const float* __restrict__ cWs, const float* __restrict__ cbs) {
    __shared__ float eta_sm[ETAD];
    __shared__ float h_sm[CH];
    int b = blockIdx.x;
    int t = threadIdx.x;
    if (t < ETAD) eta_sm[t] = eta[b*ETAD + t];
    __syncthreads();
    float acc = cb1[t];
    #pragma unroll 16
    for (int e = 0; e < ETAD; e++) acc = fmaf(eta_sm[e], cW1[e*CH + t], acc);
    h_sm[t] = fmaxf(acc, 0.f);
    __syncthreads();
    if (t < KK) {
        float s = cb2[t] + cbs[t];
        #pragma unroll 16
        for (int j = 0; j < CH; j++) s = fmaf(h_sm[j], cW2[j*KK + t], s);
        #pragma unroll 16
        for (int e = 0; e < ETAD; e++) s = fmaf(eta_sm[e], cWs[e*KK + t], s);
        g_s[b*KK + t] = s;
    }
}

/* -------- kernel 2: warp handles 4 nodes; weights reused across nodes -------- */
__global__ __launch_bounds__(256)
void k_node(const float* __restrict__ gum, const float* __restrict__ zn,
            const float* __restrict__ cm,  const float* __restrict__ cls,
            const float* __restrict__ aW1, const float* __restrict__ ab1,
            const float* __restrict__ aW2, const float* __restrict__ ab2,
            const float* __restrict__ aWs, const float* __restrict__ absk,
            float* __restrict__ atom_out) {
    __shared__ float4 w1s4[ZDIM*32];                 /* [d][lane] float4, 16KB */
    __shared__ __align__(16) float aw2t[NA*AH];      /* transposed [o][j], 5KB */
    __shared__ __align__(16) float awst[NA*ZDIM];    /* transposed [o][d]      */
    __shared__ float4 ab1s4[32];
    __shared__ float  ab2s[NA];
    __shared__ __align__(16) float zsm[8][4][ZDIM];  /* 4KB  */
    __shared__ __align__(16) float hsm[8][4][AH];    /* 16KB */

    int tid  = threadIdx.x;
    int warp = tid >> 5;
    int lane = tid & 31;

    for (int i = tid; i < ZDIM*32; i += 256) w1s4[i] = ((const float4*)aW1)[i];
    for (int i = tid; i < NA*AH;  i += 256) { int o = i / AH, j = i % AH; aw2t[i] = aW2[j*NA + o]; }
    for (int i = tid; i < NA*ZDIM; i += 256) { int o = i / ZDIM, d = i % ZDIM; awst[i] = aWs[d*NA + o]; }
    if (tid < 32) ab1s4[tid] = ((const float4*)ab1)[tid];
    if (tid < NA) ab2s[tid]  = ab2[tid] + absk[tid];
    __syncthreads();

    int node0 = blockIdx.x * 32 + warp;

    /* phase 1: argmax + z for the warp's 4 nodes */
    #pragma unroll
    for (int u = 0; u < 4; u++) {
        int node = node0 + u*8;
        int b = (unsigned)node / NN;
        float val = g_s[b*KK + lane] + gum[node*KK + lane];
        int idx = lane;
        #pragma unroll
        for (int off = 16; off; off >>= 1) {
            float ov = __shfl_xor_sync(0xffffffffu, val, off);
            int   oi = __shfl_xor_sync(0xffffffffu, idx, off);
            if (ov > val || (ov == val && oi < idx)) { val = ov; idx = oi; }
        }
        int kmax = idx;
        float ls = cls[kmax*ZDIM + lane];
        float sg = __expf(fminf(fmaxf(ls, -20.f), 30.f));
        float z  = fmaf(zn[node*ZDIM + lane], sg, cm[kmax*ZDIM + lane]);
        g_z[node*ZDIM + lane] = z;
        zsm[warp][u][lane] = z;
    }
    __syncwarp();

    /* phase 2: hidden layer, one weight load serves 4 nodes */
    float4 acc0 = ab1s4[lane], acc1 = acc0, acc2 = acc0, acc3 = acc0;
    #pragma unroll
    for (int d = 0; d < ZDIM; d++) {
        float4 w = w1s4[d*32 + lane];
        float z0 = zsm[warp][0][d], z1 = zsm[warp][1][d];
        float z2 = zsm[warp][2][d], z3 = zsm[warp][3][d];
        acc0.x = fmaf(z0, w.x, acc0.x); acc0.y = fmaf(z0, w.y, acc0.y);
        acc0.z = fmaf(z0, w.z, acc0.z); acc0.w = fmaf(z0, w.w, acc0.w);
        acc1.x = fmaf(z1, w.x, acc1.x); acc1.y = fmaf(z1, w.y, acc1.y);
        acc1.z = fmaf(z1, w.z, acc1.z); acc1.w = fmaf(z1, w.w, acc1.w);
        acc2.x = fmaf(z2, w.x, acc2.x); acc2.y = fmaf(z2, w.y, acc2.y);
        acc2.z = fmaf(z2, w.z, acc2.z); acc2.w = fmaf(z2, w.w, acc2.w);
        acc3.x = fmaf(z3, w.x, acc3.x); acc3.y = fmaf(z3, w.y, acc3.y);
        acc3.z = fmaf(z3, w.z, acc3.z); acc3.w = fmaf(z3, w.w, acc3.w);
    }
    #define RELU4(a) { a.x=fmaxf(a.x,0.f); a.y=fmaxf(a.y,0.f); a.z=fmaxf(a.z,0.f); a.w=fmaxf(a.w,0.f); }
    RELU4(acc0) RELU4(acc1) RELU4(acc2) RELU4(acc3)
    reinterpret_cast<float4*>(hsm[warp][0])[lane] = acc0;
    reinterpret_cast<float4*>(hsm[warp][1])[lane] = acc1;
    reinterpret_cast<float4*>(hsm[warp][2])[lane] = acc2;
    reinterpret_cast<float4*>(hsm[warp][3])[lane] = acc3;
    __syncwarp();

    /* phase 3: output layer, all lanes: 40 (node,out) pairs over 2 passes */
    #pragma unroll
    for (int pass = 0; pass < 2; pass++) {
        int q = pass*32 + lane;
        if (q < 40) {
            int u = q / 10, o = q % 10;
            float s = ab2s[o];
            #pragma unroll 8
            for (int j4 = 0; j4 < AH/4; j4++) {
                float4 h = *reinterpret_cast<const float4*>(&hsm[warp][u][j4*4]);
                float4 w = *reinterpret_cast<const float4*>(&aw2t[o*AH + j4*4]);
                s = fmaf(h.x, w.x, fmaf(h.y, w.y, fmaf(h.z, w.z, fmaf(h.w, w.w, s))));
            }
            #pragma unroll
            for (int d4 = 0; d4 < ZDIM/4; d4++) {
                float4 zv = *reinterpret_cast<const float4*>(&zsm[warp][u][d4*4]);
                float4 w  = *reinterpret_cast<const float4*>(&awst[o*ZDIM + d4*4]);
                s = fmaf(zv.x, w.x, fmaf(zv.y, w.y, fmaf(zv.z, w.z, fmaf(zv.w, w.w, s))));
            }
            atom_out[(node0 + u*8)*NA + o] = s;
        }
    }
}

/* -------- kernel 3: block-per-batch edges; 2 edges packed in f32x2 -------- */
__global__ __launch_bounds__(256, 3)
void k_edge(const float* __restrict__ bW1, const float* __restrict__ bb1,
            const float* __restrict__ bW2, const float* __restrict__ bb2,
            const float* __restrict__ bWs, const float* __restrict__ bbs,
            float* __restrict__ edge_out) {
    __shared__ __align__(16) float zs[NN*ZPAD];
    __shared__ __align__(16) float vs[NB*NN*ZPAD];
    __shared__ __align__(16) unsigned long long w1d[NB*BH];  /* (w,w) dup */
    __shared__ __align__(16) unsigned long long w2d[NB*BH];  /* transposed, dup */
    __shared__ __align__(16) unsigned long long b1d[BH];
    __shared__ float wss_s[NB*NB];
    __shared__ float b2s[NB];

    int b   = blockIdx.x;
    int tid = threadIdx.x;

    for (int i = tid; i < NB*BH; i += 256) {
        float w1v = bW1[i];
        w1d[i] = pk2(w1v, w1v);
        int t = i >> 6, j = i & 63;
        float w2v = bW2[j*NB + t];
        w2d[i] = pk2(w2v, w2v);
    }
    if (tid < BH)    { float bv = bb1[tid]; b1d[tid] = pk2(bv, bv); }
    if (tid < NB*NB) wss_s[tid] = bWs[tid];
    if (tid < NB)    b2s[tid]   = bb2[tid] + bbs[tid];

    for (int i = tid; i < NN*8; i += 256) {
        int n = i >> 3, d4 = i & 7;
        *reinterpret_cast<float4*>(&zs[n*ZPAD + d4*4]) =
            reinterpret_cast<const float4*>(g_z)[(size_t)b*NN*8 + i];
    }
    __syncthreads();

    /* v[t][j][d] = sum_c Wsym[t][c][d] * z[j][c] */
    for (int base = 0; base < NN*8; base += 256) {
        int idx = base + tid;
        if (idx < NN*8) {
            int j = idx >> 3, d4 = idx & 7;
            #pragma unroll
            for (int t = 0; t < NB; t++) {
                float4 acc = make_float4(0.f, 0.f, 0.f, 0.f);
                const float4* W = reinterpret_cast<const float4*>(g_wsym) + t*256 + d4;
                #pragma unroll 8
                for (int c = 0; c < ZDIM; c++) {
                    float zc = zs[j*ZPAD + c];
                    float4 w = W[c*8];
                    acc.x = fmaf(zc, w.x, acc.x);
                    acc.y = fmaf(zc, w.y, acc.y);
                    acc.z = fmaf(zc, w.z, acc.z);
                    acc.w = fmaf(zc, w.w, acc.w);
                }
                *reinterpret_cast<float4*>(&vs[t*NN*ZPAD + j*ZPAD + d4*4]) = acc;
            }
        }
    }
    __syncthreads();

    float* outb = edge_out + (size_t)b * EPB * NB;

    for (int p = tid; p < HPAIR; p += 256) {
        int eA = p, eB = p + HPAIR;
        int iiA, jjA, iiB, jjB;
        edecode(eA, iiA, jjA);
        edecode(eB, iiB, jjB);

        /* bilinear per edge (sequential to cap live registers) */
        float bilA[NB], bilB[NB];
        {
            float4 ac[NB];
            #pragma unroll
            for (int t = 0; t < NB; t++) ac[t] = make_float4(0.f, 0.f, 0.f, 0.f);
            #pragma unroll
            for (int d4 = 0; d4 < 8; d4++) {
                float4 zi = *reinterpret_cast<const float4*>(&zs[iiA*ZPAD + d4*4]);
                #pragma unroll
                for (int t = 0; t < NB; t++) {
                    float4 v = *reinterpret_cast<const float4*>(&vs[t*NN*ZPAD + jjA*ZPAD + d4*4]);
                    ac[t].x = fmaf(zi.x, v.x, ac[t].x);
                    ac[t].y = fmaf(zi.y, v.y, ac[t].y);
                    ac[t].z = fmaf(zi.z, v.z, ac[t].z);
                    ac[t].w = fmaf(zi.w, v.w, ac[t].w);
                }
            }
            #pragma unroll
            for (int t = 0; t < NB; t++) bilA[t] = (ac[t].x + ac[t].y) + (ac[t].z + ac[t].w);
        }
        {
            float4 ac[NB];
            #pragma unroll
            for (int t = 0; t < NB; t++) ac[t] = make_float4(0.f, 0.f, 0.f, 0.f);
            #pragma unroll
            for (int d4 = 0; d4 < 8; d4++) {
                float4 zi = *reinterpret_cast<const float4*>(&zs[iiB*ZPAD + d4*4]);
                #pragma unroll
                for (int t = 0; t < NB; t++) {
                    float4 v = *reinterpret_cast<const float4*>(&vs[t*NN*ZPAD + jjB*ZPAD + d4*4]);
                    ac[t].x = fmaf(zi.x, v.x, ac[t].x);
                    ac[t].y = fmaf(zi.y, v.y, ac[t].y);
                    ac[t].z = fmaf(zi.z, v.z, ac[t].z);
                    ac[t].w = fmaf(zi.w, v.w, ac[t].w);
                }
            }
            #pragma unroll
            for (int t = 0; t < NB; t++) bilB[t] = (ac[t].x + ac[t].y) + (ac[t].z + ac[t].w);
        }

        /* skip path + pack (A in lo, B in hi) */
        unsigned long long oo2[NB], bil2[NB];
        #pragma unroll
        for (int t = 0; t < NB; t++) {
            float sa = b2s[t], sb = b2s[t];
            #pragma unroll
            for (int u = 0; u < NB; u++) {
                sa = fmaf(bilA[u], wss_s[u*NB + t], sa);
                sb = fmaf(bilB[u], wss_s[u*NB + t], sb);
            }
            oo2[t]  = pk2(sa, sb);
            bil2[t] = pk2(bilA[t], bilB[t]);
        }

        /* MLP: one hidden unit per iteration, both edges packed */
        #pragma unroll 2
        for (int j = 0; j < BH; j++) {
            unsigned long long h = b1d[j];
            #pragma unroll
            for (int t = 0; t < NB; t++) h = fma2(bil2[t], w1d[t*BH + j], h);
            { float x, y; upk2(h, x, y); h = pk2(fmaxf(x, 0.f), fmaxf(y, 0.f)); }
            #pragma unroll
            for (int t = 0; t < NB; t++) oo2[t] = fma2(h, w2d[t*BH + j], oo2[t]);
        }

        /* unpack, softmax, store */
        float oA[NB], oB[NB];
        #pragma unroll
        for (int t = 0; t < NB; t++) upk2(oo2[t], oA[t], oB[t]);
        {
            float m = oA[0];
            #pragma unroll
            for (int t = 1; t < NB; t++) m = fmaxf(m, oA[t]);
            float s = 0.f, ex[NB];
            #pragma unroll
            for (int t = 0; t < NB; t++) { ex[t] = __expf(oA[t] - m); s += ex[t]; }
            float inv = __fdividef(1.f, s);
            #pragma unroll
            for (int t = 0; t < NB; t++) outb[eA*NB + t] = ex[t] * inv;
        }
        {
            float m = oB[0];
            #pragma unroll
            for (int t = 1; t < NB; t++) m = fmaxf(m, oB[t]);
            float s = 0.f, ex[NB];
            #pragma unroll
            for (int t = 0; t < NB; t++) { ex[t] = __expf(oB[t] - m); s += ex[t]; }
            float inv = __fdividef(1.f, s);
            #pragma unroll
            for (int t = 0; t < NB; t++) outb[eB*NB + t] = ex[t] * inv;
        }
    }
}

/* ------------------------- launch ------------------------- */
extern "C" void kernel_launch(void* const* d_in, const int* in_sizes, int n_in,
                              void* d_out, int out_size) {
    const float* eta  = (const float*)d_in[0];
    const float* gum  = (const float*)d_in[1];
    const float* zn   = (const float*)d_in[2];
    const float* cW1  = (const float*)d_in[3];
    const float* cb1  = (const float*)d_in[4];
    const float* cW2  = (const float*)d_in[5];
    const float* cb2  = (const float*)d_in[6];
    const float* cWs  = (const float*)d_in[7];
    const float* cbs  = (const float*)d_in[8];
    const float* cm   = (const float*)d_in[9];
    const float* cls  = (const float*)d_in[10];
    const float* aW1  = (const float*)d_in[11];
    const float* ab1  = (const float*)d_in[12];
    const float* aW2  = (const float*)d_in[13];
    const float* ab2  = (const float*)d_in[14];
    const float* aWs  = (const float*)d_in[15];
    const float* absk = (const float*)d_in[16];
    const float* bm   = (const float*)d_in[17];
    const float* bW1  = (const float*)d_in[18];
    const float* bb1  = (const float*)d_in[19];
    const float* bW2  = (const float*)d_in[20];
    const float* bb2  = (const float*)d_in[21];
    const float* bWs  = (const float*)d_in[22];
    const float* bbs  = (const float*)d_in[23];

    float* atom_out = (float*)d_out;
    float* edge_out = atom_out + (size_t)NODES * NA;

    k_wsym   <<<(NB*ZDIM*ZDIM + 255)/256, 256>>>(bm);
    k_cluster<<<BB, CH>>>(eta, cW1, cb1, cW2, cb2, cWs, cbs);
    k_node   <<<NODES/32, 256>>>(gum, zn, cm, cls, aW1, ab1, aW2, ab2, aWs, absk, atom_out);
    k_edge   <<<BB, 256>>>(bW1, bb1, bW2, bb2, bWs, bbs, edge_out);
}

// round 7
// speedup vs baseline: 1.1597x; 1.1597x over previous
#include <cuda_runtime.h>
#include <math.h>

#define BB   1024
#define NN   40
#define ETAD 64
#define KK   32
#define ZDIM 32
#define NA   10
#define NB   5
#define CH   128
#define AH   128
#define BH   64
#define NODES (BB*NN)        /* 40960 */
#define EPB   780            /* C(40,2) edges per batch */
#define ZPAD  36             /* padded row stride (floats), 16B aligned */

/* ---- scratch (static device memory; allocation-free) ---- */
__device__ __align__(16) float g_s[BB*KK];
__device__ __align__(16) float g_z[NODES*ZDIM];
__device__ __align__(16) float g_wsym[NB*ZDIM*ZDIM];
__device__ __align__(16) float g_w2t[NB*BH];          /* bW2 transposed [t][j] */

/* ---- edge-MLP weights in constant memory: uniform-address LDCU loads,
   zero L1/crossbar traffic (copied in-graph via cudaMemcpyToSymbolAsync) ---- */
__constant__ __align__(16) float c_bW1[NB*BH];        /* [t][j] raw            */
__constant__ __align__(16) float c_w2t[NB*BH];        /* transposed [t][j]     */
__constant__ __align__(16) float c_bb1[BH];
__constant__ __align__(16) float c_wss[NB*NB];
__constant__ __align__(16) float c_bb2[NB];
__constant__ __align__(16) float c_bbs[NB];

/* ---- f32x2 packed helpers (sm_100+) ---- */
__device__ __forceinline__ unsigned long long pk2(float lo, float hi) {
    unsigned long long r;
    asm("mov.b64 %0, {%1, %2};" : "=l"(r) : "f"(lo), "f"(hi));
    return r;
}
__device__ __forceinline__ void upk2(unsigned long long v, float& lo, float& hi) {
    asm("mov.b64 {%0, %1}, %2;" : "=f"(lo), "=f"(hi) : "l"(v));
}
__device__ __forceinline__ unsigned long long fma2(unsigned long long a,
                                                   unsigned long long b,
                                                   unsigned long long c) {
    unsigned long long r;
    asm("fma.rn.f32x2 %0, %1, %2, %3;" : "=l"(r) : "l"(a), "l"(b), "l"(c));
    return r;
}

/* lex-order edge index for pair (i<j) in a batch of NN nodes */
__device__ __forceinline__ int eidx(int i, int j) {
    return i*(2*NN - 1 - i)/2 + (j - i - 1);
}

/* ---------------- kernel 0: prep — Wsym symmetrize + bW2 transpose -------- */
__global__ void k_prep(const float* __restrict__ bm, const float* __restrict__ bW2) {
    int i = blockIdx.x * blockDim.x + threadIdx.x;
    if (i < NB*ZDIM*ZDIM) {
        int t = i / (ZDIM*ZDIM);
        int r = (i / ZDIM) % ZDIM;
        int c = i % ZDIM;
        g_wsym[i] = 0.5f * (bm[t*ZDIM*ZDIM + r*ZDIM + c] +
                            bm[t*ZDIM*ZDIM + c*ZDIM + r]);
    }
    if (i < NB*BH) {
        int t = i >> 6, j = i & 63;
        g_w2t[i] = bW2[j*NB + t];
    }
}

/* -------- kernel 1: per-batch cluster resblock logits s[b,k] -------- */
__global__ void k_cluster(const float* __restrict__ eta,
                          const float* __restrict__ cW1, const float* __restrict__ cb1,
                          const float* __restrict__ cW2, const float* __restrict__ cb2,
                          const float* __restrict__ cWs, const float* __restrict__ cbs) {
    __shared__ float eta_sm[ETAD];
    __shared__ float h_sm[CH];
    int b = blockIdx.x;
    int t = threadIdx.x;
    if (t < ETAD) eta_sm[t] = eta[b*ETAD + t];
    __syncthreads();
    float acc = cb1[t];
    #pragma unroll 16
    for (int e = 0; e < ETAD; e++) acc = fmaf(eta_sm[e], cW1[e*CH + t], acc);
    h_sm[t] = fmaxf(acc, 0.f);
    __syncthreads();
    if (t < KK) {
        float s = cb2[t] + cbs[t];
        #pragma unroll 16
        for (int j = 0; j < CH; j++) s = fmaf(h_sm[j], cW2[j*KK + t], s);
        #pragma unroll 16
        for (int e = 0; e < ETAD; e++) s = fmaf(eta_sm[e], cWs[e*KK + t], s);
        g_s[b*KK + t] = s;
    }
}

/* -------- kernel 2: warp handles 4 nodes; weights reused across nodes -------- */
__global__ __launch_bounds__(256)
void k_node(const float* __restrict__ gum, const float* __restrict__ zn,
            const float* __restrict__ cm,  const float* __restrict__ cls,
            const float* __restrict__ aW1, const float* __restrict__ ab1,
            const float* __restrict__ aW2, const float* __restrict__ ab2,
            const float* __restrict__ aWs, const float* __restrict__ absk,
            float* __restrict__ atom_out) {
    __shared__ float4 w1s4[ZDIM*32];
    __shared__ __align__(16) float aw2t[NA*AH];
    __shared__ __align__(16) float awst[NA*ZDIM];
    __shared__ float4 ab1s4[32];
    __shared__ float  ab2s[NA];
    __shared__ __align__(16) float zsm[8][4][ZDIM];
    __shared__ __align__(16) float hsm[8][4][AH];

    int tid  = threadIdx.x;
    int warp = tid >> 5;
    int lane = tid & 31;

    for (int i = tid; i < ZDIM*32; i += 256) w1s4[i] = ((const float4*)aW1)[i];
    for (int i = tid; i < NA*AH;  i += 256) { int o = i / AH, j = i % AH; aw2t[i] = aW2[j*NA + o]; }
    for (int i = tid; i < NA*ZDIM; i += 256) { int o = i / ZDIM, d = i % ZDIM; awst[i] = aWs[d*NA + o]; }
    if (tid < 32) ab1s4[tid] = ((const float4*)ab1)[tid];
    if (tid < NA) ab2s[tid]  = ab2[tid] + absk[tid];
    __syncthreads();

    int node0 = blockIdx.x * 32 + warp;

    #pragma unroll
    for (int u = 0; u < 4; u++) {
        int node = node0 + u*8;
        int b = (unsigned)node / NN;
        float val = g_s[b*KK + lane] + gum[node*KK + lane];
        int idx = lane;
        #pragma unroll
        for (int off = 16; off; off >>= 1) {
            float ov = __shfl_xor_sync(0xffffffffu, val, off);
            int   oi = __shfl_xor_sync(0xffffffffu, idx, off);
            if (ov > val || (ov == val && oi < idx)) { val = ov; idx = oi; }
        }
        int kmax = idx;
        float ls = cls[kmax*ZDIM + lane];
        float sg = __expf(fminf(fmaxf(ls, -20.f), 30.f));
        float z  = fmaf(zn[node*ZDIM + lane], sg, cm[kmax*ZDIM + lane]);
        g_z[node*ZDIM + lane] = z;
        zsm[warp][u][lane] = z;
    }
    __syncwarp();

    float4 acc0 = ab1s4[lane], acc1 = acc0, acc2 = acc0, acc3 = acc0;
    #pragma unroll
    for (int d = 0; d < ZDIM; d++) {
        float4 w = w1s4[d*32 + lane];
        float z0 = zsm[warp][0][d], z1 = zsm[warp][1][d];
        float z2 = zsm[warp][2][d], z3 = zsm[warp][3][d];
        acc0.x = fmaf(z0, w.x, acc0.x); acc0.y = fmaf(z0, w.y, acc0.y);
        acc0.z = fmaf(z0, w.z, acc0.z); acc0.w = fmaf(z0, w.w, acc0.w);
        acc1.x = fmaf(z1, w.x, acc1.x); acc1.y = fmaf(z1, w.y, acc1.y);
        acc1.z = fmaf(z1, w.z, acc1.z); acc1.w = fmaf(z1, w.w, acc1.w);
        acc2.x = fmaf(z2, w.x, acc2.x); acc2.y = fmaf(z2, w.y, acc2.y);
        acc2.z = fmaf(z2, w.z, acc2.z); acc2.w = fmaf(z2, w.w, acc2.w);
        acc3.x = fmaf(z3, w.x, acc3.x); acc3.y = fmaf(z3, w.y, acc3.y);
        acc3.z = fmaf(z3, w.z, acc3.z); acc3.w = fmaf(z3, w.w, acc3.w);
    }
    #define RELU4(a) { a.x=fmaxf(a.x,0.f); a.y=fmaxf(a.y,0.f); a.z=fmaxf(a.z,0.f); a.w=fmaxf(a.w,0.f); }
    RELU4(acc0) RELU4(acc1) RELU4(acc2) RELU4(acc3)
    reinterpret_cast<float4*>(hsm[warp][0])[lane] = acc0;
    reinterpret_cast<float4*>(hsm[warp][1])[lane] = acc1;
    reinterpret_cast<float4*>(hsm[warp][2])[lane] = acc2;
    reinterpret_cast<float4*>(hsm[warp][3])[lane] = acc3;
    __syncwarp();

    #pragma unroll
    for (int pass = 0; pass < 2; pass++) {
        int q = pass*32 + lane;
        if (q < 40) {
            int u = q / 10, o = q % 10;
            float s = ab2s[o];
            #pragma unroll 8
            for (int j4 = 0; j4 < AH/4; j4++) {
                float4 h = *reinterpret_cast<const float4*>(&hsm[warp][u][j4*4]);
                float4 w = *reinterpret_cast<const float4*>(&aw2t[o*AH + j4*4]);
                s = fmaf(h.x, w.x, fmaf(h.y, w.y, fmaf(h.z, w.z, fmaf(h.w, w.w, s))));
            }
            #pragma unroll
            for (int d4 = 0; d4 < ZDIM/4; d4++) {
                float4 zv = *reinterpret_cast<const float4*>(&zsm[warp][u][d4*4]);
                float4 w  = *reinterpret_cast<const float4*>(&awst[o*ZDIM + d4*4]);
                s = fmaf(zv.x, w.x, fmaf(zv.y, w.y, fmaf(zv.z, w.z, fmaf(zv.w, w.w, s))));
            }
            atom_out[(node0 + u*8)*NA + o] = s;
        }
    }
}

/* -------- kernel 3: edges; (i0,i1|j) tiles, constant weights, f32x2 MLP ---- */
/* 400 work items per batch: 380 tiles (2 edges sharing v[t][j]) + 20 singles. */
__global__ __launch_bounds__(256, 3)
void k_edge(float* __restrict__ edge_out) {
    __shared__ __align__(16) float zs[NN*ZPAD];
    __shared__ __align__(16) float vs[NB*NN*ZPAD];

    int b   = blockIdx.x;
    int tid = threadIdx.x;

    for (int i = tid; i < NN*8; i += 256) {
        int n = i >> 3, d4 = i & 7;
        *reinterpret_cast<float4*>(&zs[n*ZPAD + d4*4]) =
            reinterpret_cast<const float4*>(g_z)[(size_t)b*NN*8 + i];
    }
    __syncthreads();

    /* v[t][j][d] = sum_c Wsym[t][c][d] * z[j][c] */
    for (int base = 0; base < NN*8; base += 256) {
        int idx = base + tid;
        if (idx < NN*8) {
            int j = idx >> 3, d4 = idx & 7;
            #pragma unroll
            for (int t = 0; t < NB; t++) {
                float4 acc = make_float4(0.f, 0.f, 0.f, 0.f);
                const float4* W = reinterpret_cast<const float4*>(g_wsym) + t*256 + d4;
                #pragma unroll 8
                for (int c = 0; c < ZDIM; c++) {
                    float zc = zs[j*ZPAD + c];
                    float4 w = W[c*8];
                    acc.x = fmaf(zc, w.x, acc.x);
                    acc.y = fmaf(zc, w.y, acc.y);
                    acc.z = fmaf(zc, w.z, acc.z);
                    acc.w = fmaf(zc, w.w, acc.w);
                }
                *reinterpret_cast<float4*>(&vs[t*NN*ZPAD + j*ZPAD + d4*4]) = acc;
            }
        }
    }
    __syncthreads();

    float* outb = edge_out + (size_t)b * EPB * NB;

    for (int w = tid; w < 400; w += 256) {
        int i0, i1, j;
        if (w < 380) {
            /* tiles: I in 0..18, j in 2I+2..39; cum C(I) = I*(39-I) */
            int I = (int)(19.5f - sqrtf(380.25f - (float)w));
            if (I > 18) I = 18;
            if (I < 0)  I = 0;
            int c = I*(39 - I);
            if (w < c)  { I--; c = I*(39 - I); }
            else        { int c2 = (I + 1)*(38 - I); if (w >= c2) { I++; c = c2; } }
            j  = 2*I + 2 + (w - c);
            i0 = 2*I; i1 = 2*I + 1;
        } else {
            int I = w - 380;
            i0 = 2*I; i1 = 2*I; j = 2*I + 1;   /* single edge, duplicate halves */
        }
        int e0 = eidx(i0, j), e1 = eidx(i1, j);

        /* ---- bilinear: v row shared across both edges ---- */
        float bil0[NB], bil1[NB];
        #pragma unroll
        for (int t = 0; t < NB; t++) { bil0[t] = 0.f; bil1[t] = 0.f; }
        #pragma unroll
        for (int d4 = 0; d4 < 8; d4++) {
            float4 z0 = *reinterpret_cast<const float4*>(&zs[i0*ZPAD + d4*4]);
            float4 z1 = *reinterpret_cast<const float4*>(&zs[i1*ZPAD + d4*4]);
            #pragma unroll
            for (int t = 0; t < NB; t++) {
                float4 v = *reinterpret_cast<const float4*>(&vs[t*NN*ZPAD + j*ZPAD + d4*4]);
                bil0[t] = fmaf(z0.w, v.w, fmaf(z0.z, v.z, fmaf(z0.y, v.y, fmaf(z0.x, v.x, bil0[t]))));
                bil1[t] = fmaf(z1.w, v.w, fmaf(z1.z, v.z, fmaf(z1.y, v.y, fmaf(z1.x, v.x, bil1[t]))));
            }
        }

        /* ---- skip path + pack (hidden-pair scheme: lo=even j, hi=odd j) ---- */
        unsigned long long oo0[NB], oo1[NB], bp0[NB], bp1[NB];
        #pragma unroll
        for (int t = 0; t < NB; t++) {
            float base = c_bb2[t] + c_bbs[t];
            float s0 = base, s1 = base;
            #pragma unroll
            for (int u = 0; u < NB; u++) {
                s0 = fmaf(bil0[u], c_wss[u*NB + t], s0);
                s1 = fmaf(bil1[u], c_wss[u*NB + t], s1);
            }
            oo0[t] = pk2(s0, 0.f);
            oo1[t] = pk2(s1, 0.f);
            bp0[t] = pk2(bil0[t], bil0[t]);
            bp1[t] = pk2(bil1[t], bil1[t]);
        }

        /* ---- MLP: hidden pairs, weights via uniform constant loads ---- */
        #pragma unroll 4
        for (int jp = 0; jp < BH/2; jp++) {
            unsigned long long b1p = *reinterpret_cast<const unsigned long long*>(&c_bb1[2*jp]);
            unsigned long long h0 = b1p, h1 = b1p;
            #pragma unroll
            for (int t = 0; t < NB; t++) {
                unsigned long long w1p =
                    *reinterpret_cast<const unsigned long long*>(&c_bW1[t*BH + 2*jp]);
                h0 = fma2(bp0[t], w1p, h0);
                h1 = fma2(bp1[t], w1p, h1);
            }
            { float x, y; upk2(h0, x, y); h0 = pk2(fmaxf(x, 0.f), fmaxf(y, 0.f)); }
            { float x, y; upk2(h1, x, y); h1 = pk2(fmaxf(x, 0.f), fmaxf(y, 0.f)); }
            #pragma unroll
            for (int t = 0; t < NB; t++) {
                unsigned long long w2p =
                    *reinterpret_cast<const unsigned long long*>(&c_w2t[t*BH + 2*jp]);
                oo0[t] = fma2(h0, w2p, oo0[t]);
                oo1[t] = fma2(h1, w2p, oo1[t]);
            }
        }

        /* ---- reduce halves, softmax, store ---- */
        {
            float o[NB];
            #pragma unroll
            for (int t = 0; t < NB; t++) { float x, y; upk2(oo0[t], x, y); o[t] = x + y; }
            float m = o[0];
            #pragma unroll
            for (int t = 1; t < NB; t++) m = fmaxf(m, o[t]);
            float s = 0.f, ex[NB];
            #pragma unroll
            for (int t = 0; t < NB; t++) { ex[t] = __expf(o[t] - m); s += ex[t]; }
            float inv = __fdividef(1.f, s);
            #pragma unroll
            for (int t = 0; t < NB; t++) outb[e0*NB + t] = ex[t] * inv;
        }
        {
            float o[NB];
            #pragma unroll
            for (int t = 0; t < NB; t++) { float x, y; upk2(oo1[t], x, y); o[t] = x + y; }
            float m = o[0];
            #pragma unroll
            for (int t = 1; t < NB; t++) m = fmaxf(m, o[t]);
            float s = 0.f, ex[NB];
            #pragma unroll
            for (int t = 0; t < NB; t++) { ex[t] = __expf(o[t] - m); s += ex[t]; }
            float inv = __fdividef(1.f, s);
            #pragma unroll
            for (int t = 0; t < NB; t++) outb[e1*NB + t] = ex[t] * inv;
        }
    }
}

/* ------------------------- launch ------------------------- */
extern "C" void kernel_launch(void* const* d_in, const int* in_sizes, int n_in,
                              void* d_out, int out_size) {
    const float* eta  = (const float*)d_in[0];
    const float* gum  = (const float*)d_in[1];
    const float* zn   = (const float*)d_in[2];
    const float* cW1  = (const float*)d_in[3];
    const float* cb1  = (const float*)d_in[4];
    const float* cW2  = (const float*)d_in[5];
    const float* cb2  = (const float*)d_in[6];
    const float* cWs  = (const float*)d_in[7];
    const float* cbs  = (const float*)d_in[8];
    const float* cm   = (const float*)d_in[9];
    const float* cls  = (const float*)d_in[10];
    const float* aW1  = (const float*)d_in[11];
    const float* ab1  = (const float*)d_in[12];
    const float* aW2  = (const float*)d_in[13];
    const float* ab2  = (const float*)d_in[14];
    const float* aWs  = (const float*)d_in[15];
    const float* absk = (const float*)d_in[16];
    const float* bm   = (const float*)d_in[17];
    const float* bW1  = (const float*)d_in[18];
    const float* bb1  = (const float*)d_in[19];
    const float* bW2  = (const float*)d_in[20];
    const float* bb2  = (const float*)d_in[21];
    const float* bWs  = (const float*)d_in[22];
    const float* bbs  = (const float*)d_in[23];

    float* atom_out = (float*)d_out;
    float* edge_out = atom_out + (size_t)NODES * NA;

    /* edge-MLP weights -> constant memory (D2D async copies, graph-capturable) */
    cudaMemcpyToSymbolAsync(c_bW1, bW1, NB*BH*sizeof(float), 0, cudaMemcpyDeviceToDevice, 0);
    cudaMemcpyToSymbolAsync(c_bb1, bb1, BH*sizeof(float),    0, cudaMemcpyDeviceToDevice, 0);
    cudaMemcpyToSymbolAsync(c_wss, bWs, NB*NB*sizeof(float), 0, cudaMemcpyDeviceToDevice, 0);
    cudaMemcpyToSymbolAsync(c_bb2, bb2, NB*sizeof(float),    0, cudaMemcpyDeviceToDevice, 0);
    cudaMemcpyToSymbolAsync(c_bbs, bbs, NB*sizeof(float),    0, cudaMemcpyDeviceToDevice, 0);

    k_prep<<<(NB*ZDIM*ZDIM + 255)/256, 256>>>(bm, bW2);

    void* w2t_ptr = nullptr;
    cudaGetSymbolAddress(&w2t_ptr, g_w2t);
    cudaMemcpyToSymbolAsync(c_w2t, w2t_ptr, NB*BH*sizeof(float), 0, cudaMemcpyDeviceToDevice, 0);

    k_cluster<<<BB, CH>>>(eta, cW1, cb1, cW2, cb2, cWs, cbs);
    k_node   <<<NODES/32, 256>>>(gum, zn, cm, cls, aW1, ab1, aW2, ab2, aWs, absk, atom_out);
    k_edge   <<<BB, 256>>>(edge_out);
}